// round 2
// baseline (speedup 1.0000x reference)
#include <cuda_runtime.h>
#include <cuda_bf16.h>
#include <math.h>

// Problem constants
#define NCTX   4096
#define DMODEL 1024
#define NHEAD  16
#define DHEAD  64
#define DEPTH  4
#define PFX    3072
#define LAT    1024          // NCTX - PFX
#define FFDIM  4096
#define VOCAB  32000
#define INNER  1024          // NHEAD * DHEAD

// ---------------------------------------------------------------------------
// Scratch (static __device__ globals; no runtime allocation)
// ---------------------------------------------------------------------------
__device__ float g_prefix[PFX * DMODEL];       // 12.6 MB
__device__ float g_h     [LAT * DMODEL];       // residual stream
__device__ float g_xn    [LAT * DMODEL];       // LN output
__device__ float g_q     [LAT * INNER];
__device__ float g_kvin  [LAT * 2 * INNER];    // latent K|V (cross)
__device__ float g_kvctx [PFX * 2 * INNER];    // prefix K|V (cross)
__device__ float g_attn  [LAT * INNER];
__device__ float g_ff    [LAT * FFDIM];
__device__ float g_qkv   [LAT * 3 * INNER];

// ---------------------------------------------------------------------------
// Embedding: e = tok_emb[x] + pos_emb ; split into prefix / h
// ---------------------------------------------------------------------------
__global__ void embed_kernel(const int* __restrict__ x,
                             const float* __restrict__ tok,
                             const float* __restrict__ pos)
{
    int idx = blockIdx.x * blockDim.x + threadIdx.x;   // over NCTX*DMODEL
    int n = idx >> 10;            // / 1024
    int d = idx & 1023;
    float v = tok[(size_t)x[n] * DMODEL + d] + pos[idx];
    if (n < PFX) g_prefix[(size_t)n * DMODEL + d] = v;
    else         g_h[(size_t)(n - PFX) * DMODEL + d] = v;
}

// ---------------------------------------------------------------------------
// LayerNorm over last dim (D=1024). One block per row, 256 threads.
// ---------------------------------------------------------------------------
__global__ __launch_bounds__(256) void ln_kernel(
    const float* __restrict__ in, float* __restrict__ out,
    const float* __restrict__ g, const float* __restrict__ b)
{
    int row = blockIdx.x;
    const float* p = in + (size_t)row * DMODEL;
    float vals[4];
    float s = 0.f, s2 = 0.f;
#pragma unroll
    for (int u = 0; u < 4; u++) {
        float v = p[threadIdx.x + u * 256];
        vals[u] = v; s += v; s2 += v * v;
    }
#pragma unroll
    for (int o = 16; o; o >>= 1) {
        s  += __shfl_xor_sync(0xffffffffu, s,  o);
        s2 += __shfl_xor_sync(0xffffffffu, s2, o);
    }
    __shared__ float sh[2][8];
    int wid = threadIdx.x >> 5, lane = threadIdx.x & 31;
    if (lane == 0) { sh[0][wid] = s; sh[1][wid] = s2; }
    __syncthreads();
    s = 0.f; s2 = 0.f;
#pragma unroll
    for (int w = 0; w < 8; w++) { s += sh[0][w]; s2 += sh[1][w]; }
    float mean = s * (1.f / DMODEL);
    float var  = s2 * (1.f / DMODEL) - mean * mean;
    float inv  = rsqrtf(var + 1e-5f);
#pragma unroll
    for (int u = 0; u < 4; u++) {
        int d = threadIdx.x + u * 256;
        out[(size_t)row * DMODEL + d] = (vals[u] - mean) * inv * g[d] + b[d];
    }
}

// ---------------------------------------------------------------------------
// SGEMM: C[M,N] = A[M,K] @ B[K,N]  (all row-major, contiguous)
// 128x128 blocktile, BK=8, 256 threads, 8x8 per thread (2x2 of 4x4 frags).
// Epilogues: 0 none | 1 +bias[col]+res | 2 +res | 3 exact GELU
// All dims used are multiples of 128 (M,N) and 8 (K) -> no bounds checks.
// ---------------------------------------------------------------------------
template <int EPI>
__global__ __launch_bounds__(256) void sgemm_kernel(
    const float* __restrict__ A, const float* __restrict__ B,
    float* __restrict__ C, const float* __restrict__ bias,
    const float* __restrict__ res, int M, int Nn, int K)
{
    __shared__ float As[8][128];
    __shared__ float Bs[8][128];

    const int tid = threadIdx.x;
    const int bx = blockIdx.x, by = blockIdx.y;

    const float* Ab = A + (size_t)by * 128 * K;
    const float* Bb = B + (size_t)bx * 128;

    const int arow = tid >> 1, acol = (tid & 1) * 4;
    const int brow = tid >> 5, bcol = (tid & 31) * 4;
    const int tx = tid & 15,  ty = tid >> 4;

    float acc[2][2][4][4];
#pragma unroll
    for (int a = 0; a < 2; a++)
#pragma unroll
        for (int c = 0; c < 2; c++)
#pragma unroll
            for (int i = 0; i < 4; i++)
#pragma unroll
                for (int j = 0; j < 4; j++) acc[a][c][i][j] = 0.f;

    for (int k0 = 0; k0 < K; k0 += 8) {
        float4 a4 = *reinterpret_cast<const float4*>(Ab + (size_t)arow * K + k0 + acol);
        As[acol + 0][arow] = a4.x;
        As[acol + 1][arow] = a4.y;
        As[acol + 2][arow] = a4.z;
        As[acol + 3][arow] = a4.w;
        float4 b4 = *reinterpret_cast<const float4*>(Bb + (size_t)(k0 + brow) * Nn + bcol);
        *reinterpret_cast<float4*>(&Bs[brow][bcol]) = b4;
        __syncthreads();
#pragma unroll
        for (int kk = 0; kk < 8; kk++) {
            float a[8], b[8];
            *reinterpret_cast<float4*>(&a[0]) = *reinterpret_cast<const float4*>(&As[kk][ty * 4]);
            *reinterpret_cast<float4*>(&a[4]) = *reinterpret_cast<const float4*>(&As[kk][64 + ty * 4]);
            *reinterpret_cast<float4*>(&b[0]) = *reinterpret_cast<const float4*>(&Bs[kk][tx * 4]);
            *reinterpret_cast<float4*>(&b[4]) = *reinterpret_cast<const float4*>(&Bs[kk][64 + tx * 4]);
#pragma unroll
            for (int ai = 0; ai < 2; ai++)
#pragma unroll
                for (int bi = 0; bi < 2; bi++)
#pragma unroll
                    for (int i = 0; i < 4; i++)
#pragma unroll
                        for (int j = 0; j < 4; j++)
                            acc[ai][bi][i][j] += a[ai * 4 + i] * b[bi * 4 + j];
        }
        __syncthreads();
    }

#pragma unroll
    for (int ai = 0; ai < 2; ai++)
#pragma unroll
        for (int i = 0; i < 4; i++) {
            int row = by * 128 + ai * 64 + ty * 4 + i;
#pragma unroll
            for (int bi = 0; bi < 2; bi++) {
                int col = bx * 128 + bi * 64 + tx * 4;
                float4 o;
                float* op = &o.x;
#pragma unroll
                for (int j = 0; j < 4; j++) {
                    float v = acc[ai][bi][i][j];
                    if (EPI == 1) v += bias[col + j] + res[(size_t)row * Nn + col + j];
                    if (EPI == 2) v += res[(size_t)row * Nn + col + j];
                    if (EPI == 3) v = 0.5f * v * (1.f + erff(v * 0.70710678f));
                    op[j] = v;
                }
                *reinterpret_cast<float4*>(C + (size_t)row * Nn + col) = o;
            }
        }
}

// ---------------------------------------------------------------------------
// Tiled attention (flash-style). One block = (head, 64-query tile).
// 8 warps x 8 queries/warp. K/V staged in 32x64 smem tiles shared by all
// 64 queries (cuts K/V L2 traffic x64 vs per-warp streaming).
// Lane l owns dims l and l+32 of the 64-dim head -> conflict-free smem reads.
// CROSS=1: q from g_q (stride 1024); KV row j: j<PFX -> kvctx else kvin,
//          row layout [K(1024)|V(1024)], causal bound j <= i+PFX.
// CROSS=0: qkv rows [Q|K|V] stride 3072, bound j <= i.
// ---------------------------------------------------------------------------
template <int CROSS>
__global__ __launch_bounds__(256) void attn_kernel(
    const float* __restrict__ qsrc, const float* __restrict__ kv0,
    const float* __restrict__ kv1, float* __restrict__ out)
{
    const int OFF     = CROSS ? PFX : 0;
    const int QSTRIDE = CROSS ? INNER : 3 * INNER;

    const int hbase = blockIdx.y * DHEAD;
    const int qbase = blockIdx.x * 64;
    const int wid = threadIdx.x >> 5, lane = threadIdx.x & 31;
    const int ibase = qbase + wid * 8;

    __shared__ float Ks[32][64];
    __shared__ float Vs[32][64];

    float q0[8], q1[8], m[8], den[8], a0[8], a1[8];
#pragma unroll
    for (int qq = 0; qq < 8; qq++) {
        const float* qp = qsrc + (size_t)(ibase + qq) * QSTRIDE + hbase;
        q0[qq] = qp[lane] * 0.125f;
        q1[qq] = qp[lane + 32] * 0.125f;
        m[qq] = -3.4e38f; den[qq] = 0.f; a0[qq] = 0.f; a1[qq] = 0.f;
    }

    const int kmax   = qbase + 63 + OFF + 1;   // exclusive key bound for block
    const int nfull  = (qbase + OFF + 1) / 32; // tiles valid for ALL queries
    const int ntiles = (kmax + 31) / 32;

    for (int t = 0; t < ntiles; t++) {
        const int jt = t * 32;
        __syncthreads();
        // Load 32 KV rows: warp w loads rows 4w..4w+3; lanes 0-15 -> K float4s,
        // lanes 16-31 -> V float4s.
#pragma unroll
        for (int r = 0; r < 4; r++) {
            int rr = wid * 4 + r;
            int j = jt + rr;
            const float *kp, *vp;
            if (CROSS) {
                const float* base = (j < PFX) ? (kv0 + (size_t)j * 2048)
                                              : (kv1 + (size_t)(j - PFX) * 2048);
                kp = base + hbase; vp = base + INNER + hbase;
            } else {
                kp = kv0 + (size_t)j * 3072 + INNER + hbase;
                vp = kp + INNER;
            }
            if (lane < 16)
                *reinterpret_cast<float4*>(&Ks[rr][lane * 4]) =
                    *reinterpret_cast<const float4*>(kp + lane * 4);
            else
                *reinterpret_cast<float4*>(&Vs[rr][(lane - 16) * 4]) =
                    *reinterpret_cast<const float4*>(vp + (lane - 16) * 4);
        }
        __syncthreads();

        if (t < nfull) {
            // full tile: no causal predicate
            for (int kk = 0; kk < 32; kk++) {
                float k0 = Ks[kk][lane], k1 = Ks[kk][lane + 32];
                float v0 = Vs[kk][lane], v1 = Vs[kk][lane + 32];
#pragma unroll
                for (int qq = 0; qq < 8; qq++) {
                    float pd = q0[qq] * k0 + q1[qq] * k1;
#pragma unroll
                    for (int o = 16; o; o >>= 1)
                        pd += __shfl_xor_sync(0xffffffffu, pd, o);
                    float mn = fmaxf(m[qq], pd);
                    float c = __expf(m[qq] - mn);
                    float p = __expf(pd - mn);
                    den[qq] = den[qq] * c + p;
                    a0[qq]  = a0[qq]  * c + p * v0;
                    a1[qq]  = a1[qq]  * c + p * v1;
                    m[qq] = mn;
                }
            }
        } else {
            // boundary tile: per-(q,key) causal predicate (warp-uniform branch)
            for (int kk = 0; kk < 32; kk++) {
                int j = jt + kk;
                float k0 = Ks[kk][lane], k1 = Ks[kk][lane + 32];
                float v0 = Vs[kk][lane], v1 = Vs[kk][lane + 32];
#pragma unroll
                for (int qq = 0; qq < 8; qq++) {
                    if (j > ibase + qq + OFF) continue;
                    float pd = q0[qq] * k0 + q1[qq] * k1;
#pragma unroll
                    for (int o = 16; o; o >>= 1)
                        pd += __shfl_xor_sync(0xffffffffu, pd, o);
                    float mn = fmaxf(m[qq], pd);
                    float c = __expf(m[qq] - mn);
                    float p = __expf(pd - mn);
                    den[qq] = den[qq] * c + p;
                    a0[qq]  = a0[qq]  * c + p * v0;
                    a1[qq]  = a1[qq]  * c + p * v1;
                    m[qq] = mn;
                }
            }
        }
    }

#pragma unroll
    for (int qq = 0; qq < 8; qq++) {
        float r = 1.f / den[qq];
        out[(size_t)(ibase + qq) * INNER + hbase + lane]      = a0[qq] * r;
        out[(size_t)(ibase + qq) * INNER + hbase + lane + 32] = a1[qq] * r;
    }
}

// ---------------------------------------------------------------------------
// Host orchestration
// ---------------------------------------------------------------------------
static void run_sgemm(int epi, const float* A, const float* B, float* C,
                      const float* bias, const float* res, int M, int Nn, int K)
{
    dim3 grid(Nn / 128, M / 128);
    switch (epi) {
        case 0: sgemm_kernel<0><<<grid, 256>>>(A, B, C, bias, res, M, Nn, K); break;
        case 1: sgemm_kernel<1><<<grid, 256>>>(A, B, C, bias, res, M, Nn, K); break;
        case 2: sgemm_kernel<2><<<grid, 256>>>(A, B, C, bias, res, M, Nn, K); break;
        case 3: sgemm_kernel<3><<<grid, 256>>>(A, B, C, bias, res, M, Nn, K); break;
    }
}

extern "C" void kernel_launch(void* const* d_in, const int* in_sizes, int n_in,
                              void* d_out, int out_size)
{
    (void)in_sizes; (void)n_in; (void)out_size;

    const int*   x        = (const int*)  d_in[0];
    const float* tok_emb  = (const float*)d_in[1];
    const float* pos_emb  = (const float*)d_in[2];
    const float* ca_ln_g  = (const float*)d_in[3];
    const float* ca_ln_b  = (const float*)d_in[4];
    const float* ca_wq    = (const float*)d_in[5];
    const float* ca_wkv   = (const float*)d_in[6];
    const float* ca_wo    = (const float*)d_in[7];
    const float* ca_bo    = (const float*)d_in[8];
    const float* cf_ln_g  = (const float*)d_in[9];
    const float* cf_ln_b  = (const float*)d_in[10];
    const float* cf_w1    = (const float*)d_in[11];
    const float* cf_w2    = (const float*)d_in[12];
    const float* la_ln_g  = (const float*)d_in[13];
    const float* la_ln_b  = (const float*)d_in[14];
    const float* la_wqkv  = (const float*)d_in[15];
    const float* la_wo    = (const float*)d_in[16];
    const float* lf_ln_g  = (const float*)d_in[17];
    const float* lf_ln_b  = (const float*)d_in[18];
    const float* lf_w1    = (const float*)d_in[19];
    const float* lf_w2    = (const float*)d_in[20];
    const float* w_logits = (const float*)d_in[21];
    float* out = (float*)d_out;

    float *prefix, *h, *xn, *q, *kvin, *kvctx, *attn, *ff, *qkv;
    cudaGetSymbolAddress((void**)&prefix, g_prefix);
    cudaGetSymbolAddress((void**)&h,      g_h);
    cudaGetSymbolAddress((void**)&xn,     g_xn);
    cudaGetSymbolAddress((void**)&q,      g_q);
    cudaGetSymbolAddress((void**)&kvin,   g_kvin);
    cudaGetSymbolAddress((void**)&kvctx,  g_kvctx);
    cudaGetSymbolAddress((void**)&attn,   g_attn);
    cudaGetSymbolAddress((void**)&ff,     g_ff);
    cudaGetSymbolAddress((void**)&qkv,    g_qkv);

    // 1. Embedding
    embed_kernel<<<(NCTX * DMODEL) / 256, 256>>>(x, tok_emb, pos_emb);

    // 2. Cross-attention block
    ln_kernel<<<LAT, 256>>>(h, xn, ca_ln_g, ca_ln_b);
    run_sgemm(0, xn,     ca_wq,  q,     nullptr, nullptr, LAT, INNER,     DMODEL);
    run_sgemm(0, xn,     ca_wkv, kvin,  nullptr, nullptr, LAT, 2 * INNER, DMODEL);
    run_sgemm(0, prefix, ca_wkv, kvctx, nullptr, nullptr, PFX, 2 * INNER, DMODEL);
    {
        dim3 g(LAT / 64, NHEAD);
        attn_kernel<1><<<g, 256>>>(q, kvctx, kvin, attn);
    }
    run_sgemm(1, attn, ca_wo, h, ca_bo, h, LAT, DMODEL, INNER);

    // 3. Cross FFN
    ln_kernel<<<LAT, 256>>>(h, xn, cf_ln_g, cf_ln_b);
    run_sgemm(3, xn, cf_w1, ff, nullptr, nullptr, LAT, FFDIM, DMODEL);
    run_sgemm(2, ff, cf_w2, h, nullptr, h, LAT, DMODEL, FFDIM);

    // 4. Latent self-attention layers
    for (int l = 0; l < DEPTH; l++) {
        ln_kernel<<<LAT, 256>>>(h, xn, la_ln_g + (size_t)l * DMODEL, la_ln_b + (size_t)l * DMODEL);
        run_sgemm(0, xn, la_wqkv + (size_t)l * DMODEL * 3 * INNER, qkv,
                  nullptr, nullptr, LAT, 3 * INNER, DMODEL);
        {
            dim3 g(LAT / 64, NHEAD);
            attn_kernel<0><<<g, 256>>>(qkv, qkv, nullptr, attn);
        }
        run_sgemm(2, attn, la_wo + (size_t)l * INNER * DMODEL, h, nullptr, h, LAT, DMODEL, INNER);

        ln_kernel<<<LAT, 256>>>(h, xn, lf_ln_g + (size_t)l * DMODEL, lf_ln_b + (size_t)l * DMODEL);
        run_sgemm(3, xn, lf_w1 + (size_t)l * DMODEL * FFDIM, ff, nullptr, nullptr, LAT, FFDIM, DMODEL);
        run_sgemm(2, ff, lf_w2 + (size_t)l * FFDIM * DMODEL, h, nullptr, h, LAT, DMODEL, FFDIM);
    }

    // 5. Logits
    run_sgemm(0, h, w_logits, out, nullptr, nullptr, LAT, VOCAB, DMODEL);
}

// round 5
// speedup vs baseline: 1.5408x; 1.5408x over previous
#include <cuda_runtime.h>
#include <cuda_bf16.h>
#include <math.h>
#include <stdint.h>

// Problem constants
#define NCTX   4096
#define DMODEL 1024
#define NHEAD  16
#define DHEAD  64
#define DEPTH  4
#define PFX    3072
#define LAT    1024          // NCTX - PFX
#define FFDIM  4096
#define VOCAB  32000
#define INNER  1024          // NHEAD * DHEAD

// ---------------------------------------------------------------------------
// Scratch (static __device__ globals; no runtime allocation)
// ---------------------------------------------------------------------------
__device__ float g_prefix[PFX * DMODEL];
__device__ float g_h     [LAT * DMODEL];
__device__ float g_xn    [LAT * DMODEL];
__device__ float g_q     [LAT * INNER];
__device__ float g_kvin  [LAT * 2 * INNER];
__device__ float g_kvctx [PFX * 2 * INNER];
__device__ float g_attn  [LAT * INNER];
__device__ float g_ff    [LAT * FFDIM];
__device__ float g_qkv   [LAT * 3 * INNER];

// ---------------------------------------------------------------------------
// Embedding
// ---------------------------------------------------------------------------
__global__ void embed_kernel(const int* __restrict__ x,
                             const float* __restrict__ tok,
                             const float* __restrict__ pos)
{
    int idx = blockIdx.x * blockDim.x + threadIdx.x;
    int n = idx >> 10;
    int d = idx & 1023;
    float v = tok[(size_t)x[n] * DMODEL + d] + pos[idx];
    if (n < PFX) g_prefix[(size_t)n * DMODEL + d] = v;
    else         g_h[(size_t)(n - PFX) * DMODEL + d] = v;
}

// ---------------------------------------------------------------------------
// LayerNorm (D=1024), one block per row
// ---------------------------------------------------------------------------
__global__ __launch_bounds__(256) void ln_kernel(
    const float* __restrict__ in, float* __restrict__ out,
    const float* __restrict__ g, const float* __restrict__ b)
{
    int row = blockIdx.x;
    const float* p = in + (size_t)row * DMODEL;
    float vals[4];
    float s = 0.f, s2 = 0.f;
#pragma unroll
    for (int u = 0; u < 4; u++) {
        float v = p[threadIdx.x + u * 256];
        vals[u] = v; s += v; s2 += v * v;
    }
#pragma unroll
    for (int o = 16; o; o >>= 1) {
        s  += __shfl_xor_sync(0xffffffffu, s,  o);
        s2 += __shfl_xor_sync(0xffffffffu, s2, o);
    }
    __shared__ float sh[2][8];
    int wid = threadIdx.x >> 5, lane = threadIdx.x & 31;
    if (lane == 0) { sh[0][wid] = s; sh[1][wid] = s2; }
    __syncthreads();
    s = 0.f; s2 = 0.f;
#pragma unroll
    for (int w = 0; w < 8; w++) { s += sh[0][w]; s2 += sh[1][w]; }
    float mean = s * (1.f / DMODEL);
    float var  = s2 * (1.f / DMODEL) - mean * mean;
    float inv  = rsqrtf(var + 1e-5f);
#pragma unroll
    for (int u = 0; u < 4; u++) {
        int d = threadIdx.x + u * 256;
        out[(size_t)row * DMODEL + d] = (vals[u] - mean) * inv * g[d] + b[d];
    }
}

// ---------------------------------------------------------------------------
// TF32 tensor-core GEMM: C[M,N] = A[M,K] @ B[K,N]  (row-major)
// mma.sync.m16n8k8 tf32, fp32 accumulate.
// Block tile 128x128, BK=16, 8 warps (4 M x 2 N), warp tile 32x64.
// Double-buffered smem, k-major with pitch 132 (bank = (4k+m)%32 -> conflict
// free fragment loads for both A and B).
// Epilogues: 0 none | 1 +bias[col]+res | 2 +res | 3 exact GELU
// ---------------------------------------------------------------------------
#define BK 16
#define SPITCH 132

__device__ __forceinline__ uint32_t f2tf(float x) {
    uint32_t r;
    asm("cvt.rna.tf32.f32 %0, %1;" : "=r"(r) : "f"(x));
    return r;
}

__device__ __forceinline__ void mma_tf32(float* d, const uint32_t* a, const uint32_t* b) {
    asm volatile(
        "mma.sync.aligned.m16n8k8.row.col.f32.tf32.tf32.f32 "
        "{%0,%1,%2,%3}, {%4,%5,%6,%7}, {%8,%9}, {%0,%1,%2,%3};"
        : "+f"(d[0]), "+f"(d[1]), "+f"(d[2]), "+f"(d[3])
        : "r"(a[0]), "r"(a[1]), "r"(a[2]), "r"(a[3]), "r"(b[0]), "r"(b[1]));
}

template <int EPI>
__global__ __launch_bounds__(256) void sgemm_kernel(
    const float* __restrict__ A, const float* __restrict__ B,
    float* __restrict__ C, const float* __restrict__ bias,
    const float* __restrict__ res, int M, int Nn, int K)
{
    __shared__ uint32_t As[2][BK][SPITCH];
    __shared__ uint32_t Bs[2][BK][SPITCH];

    const int tid  = threadIdx.x;
    const int lane = tid & 31, wid = tid >> 5;
    const int g = lane >> 2, c = lane & 3;
    const int wm = (wid & 3) * 32;   // warp M offset
    const int wn = (wid >> 2) * 64;  // warp N offset
    const int bx = blockIdx.x, by = blockIdx.y;

    // Global load mapping
    const int arow = tid >> 2;            // 0..63 (and +64)
    const int acol = (tid & 3) * 4;       // 0,4,8,12 within BK
    const int bkrow = tid >> 5;           // 0..7 (and +8)
    const int bncol = (tid & 31) * 4;     // 0..124

    const float* Ap = A + (size_t)(by * 128 + arow) * K + acol;
    const float* Bp = B + (size_t)bkrow * Nn + bx * 128 + bncol;

    float acc[2][8][4];
#pragma unroll
    for (int mf = 0; mf < 2; mf++)
#pragma unroll
        for (int nf = 0; nf < 8; nf++)
#pragma unroll
            for (int i = 0; i < 4; i++) acc[mf][nf][i] = 0.f;

    const int nt = K / BK;

    float4 pa0, pa1, pb0, pb1;
    // prefetch tile 0
    pa0 = *reinterpret_cast<const float4*>(Ap);
    pa1 = *reinterpret_cast<const float4*>(Ap + (size_t)64 * K);
    pb0 = *reinterpret_cast<const float4*>(Bp);
    pb1 = *reinterpret_cast<const float4*>(Bp + (size_t)8 * Nn);
    {
        As[0][acol + 0][arow] = f2tf(pa0.x);
        As[0][acol + 1][arow] = f2tf(pa0.y);
        As[0][acol + 2][arow] = f2tf(pa0.z);
        As[0][acol + 3][arow] = f2tf(pa0.w);
        As[0][acol + 0][arow + 64] = f2tf(pa1.x);
        As[0][acol + 1][arow + 64] = f2tf(pa1.y);
        As[0][acol + 2][arow + 64] = f2tf(pa1.z);
        As[0][acol + 3][arow + 64] = f2tf(pa1.w);
        Bs[0][bkrow][bncol + 0] = f2tf(pb0.x);
        Bs[0][bkrow][bncol + 1] = f2tf(pb0.y);
        Bs[0][bkrow][bncol + 2] = f2tf(pb0.z);
        Bs[0][bkrow][bncol + 3] = f2tf(pb0.w);
        Bs[0][bkrow + 8][bncol + 0] = f2tf(pb1.x);
        Bs[0][bkrow + 8][bncol + 1] = f2tf(pb1.y);
        Bs[0][bkrow + 8][bncol + 2] = f2tf(pb1.z);
        Bs[0][bkrow + 8][bncol + 3] = f2tf(pb1.w);
    }
    __syncthreads();

    for (int kt = 0; kt < nt; kt++) {
        const int cur = kt & 1;
        if (kt + 1 < nt) {
            const float* ap = Ap + (kt + 1) * BK;
            const float* bp = Bp + (size_t)(kt + 1) * BK * Nn;
            pa0 = *reinterpret_cast<const float4*>(ap);
            pa1 = *reinterpret_cast<const float4*>(ap + (size_t)64 * K);
            pb0 = *reinterpret_cast<const float4*>(bp);
            pb1 = *reinterpret_cast<const float4*>(bp + (size_t)8 * Nn);
        }

#pragma unroll
        for (int ks = 0; ks < 2; ks++) {
            const int k0 = ks * 8;
            uint32_t af[2][4], bf[8][2];
#pragma unroll
            for (int mf = 0; mf < 2; mf++) {
                int mrow = wm + mf * 16 + g;
                af[mf][0] = As[cur][k0 + c][mrow];
                af[mf][1] = As[cur][k0 + c][mrow + 8];
                af[mf][2] = As[cur][k0 + c + 4][mrow];
                af[mf][3] = As[cur][k0 + c + 4][mrow + 8];
            }
#pragma unroll
            for (int nf = 0; nf < 8; nf++) {
                int ncol = wn + nf * 8 + g;
                bf[nf][0] = Bs[cur][k0 + c][ncol];
                bf[nf][1] = Bs[cur][k0 + c + 4][ncol];
            }
#pragma unroll
            for (int mf = 0; mf < 2; mf++)
#pragma unroll
                for (int nf = 0; nf < 8; nf++)
                    mma_tf32(acc[mf][nf], af[mf], bf[nf]);
        }

        if (kt + 1 < nt) {
            const int nxt = cur ^ 1;
            As[nxt][acol + 0][arow] = f2tf(pa0.x);
            As[nxt][acol + 1][arow] = f2tf(pa0.y);
            As[nxt][acol + 2][arow] = f2tf(pa0.z);
            As[nxt][acol + 3][arow] = f2tf(pa0.w);
            As[nxt][acol + 0][arow + 64] = f2tf(pa1.x);
            As[nxt][acol + 1][arow + 64] = f2tf(pa1.y);
            As[nxt][acol + 2][arow + 64] = f2tf(pa1.z);
            As[nxt][acol + 3][arow + 64] = f2tf(pa1.w);
            Bs[nxt][bkrow][bncol + 0] = f2tf(pb0.x);
            Bs[nxt][bkrow][bncol + 1] = f2tf(pb0.y);
            Bs[nxt][bkrow][bncol + 2] = f2tf(pb0.z);
            Bs[nxt][bkrow][bncol + 3] = f2tf(pb0.w);
            Bs[nxt][bkrow + 8][bncol + 0] = f2tf(pb1.x);
            Bs[nxt][bkrow + 8][bncol + 1] = f2tf(pb1.y);
            Bs[nxt][bkrow + 8][bncol + 2] = f2tf(pb1.z);
            Bs[nxt][bkrow + 8][bncol + 3] = f2tf(pb1.w);
            __syncthreads();
        }
    }

    // Epilogue: C fragment c0:(g,2c) c1:(g,2c+1) c2:(g+8,2c) c3:(g+8,2c+1)
#pragma unroll
    for (int mf = 0; mf < 2; mf++) {
#pragma unroll
        for (int nf = 0; nf < 8; nf++) {
            int row = by * 128 + wm + mf * 16 + g;
            int col = bx * 128 + wn + nf * 8 + 2 * c;
#pragma unroll
            for (int half = 0; half < 2; half++) {
                int r = row + half * 8;
                float v0 = acc[mf][nf][half * 2 + 0];
                float v1 = acc[mf][nf][half * 2 + 1];
                if (EPI == 1) {
                    v0 += bias[col]     + res[(size_t)r * Nn + col];
                    v1 += bias[col + 1] + res[(size_t)r * Nn + col + 1];
                }
                if (EPI == 2) {
                    v0 += res[(size_t)r * Nn + col];
                    v1 += res[(size_t)r * Nn + col + 1];
                }
                if (EPI == 3) {
                    v0 = 0.5f * v0 * (1.f + erff(v0 * 0.70710678f));
                    v1 = 0.5f * v1 * (1.f + erff(v1 * 0.70710678f));
                }
                float2 o = make_float2(v0, v1);
                *reinterpret_cast<float2*>(C + (size_t)r * Nn + col) = o;
            }
        }
    }
}

// ---------------------------------------------------------------------------
// Tiled attention (flash-style), unchanged from passing baseline.
// ---------------------------------------------------------------------------
template <int CROSS>
__global__ __launch_bounds__(256) void attn_kernel(
    const float* __restrict__ qsrc, const float* __restrict__ kv0,
    const float* __restrict__ kv1, float* __restrict__ out)
{
    const int OFF     = CROSS ? PFX : 0;
    const int QSTRIDE = CROSS ? INNER : 3 * INNER;

    const int hbase = blockIdx.y * DHEAD;
    const int qbase = blockIdx.x * 64;
    const int wid = threadIdx.x >> 5, lane = threadIdx.x & 31;
    const int ibase = qbase + wid * 8;

    __shared__ float Ks[32][64];
    __shared__ float Vs[32][64];

    float q0[8], q1[8], m[8], den[8], a0[8], a1[8];
#pragma unroll
    for (int qq = 0; qq < 8; qq++) {
        const float* qp = qsrc + (size_t)(ibase + qq) * QSTRIDE + hbase;
        q0[qq] = qp[lane] * 0.125f;
        q1[qq] = qp[lane + 32] * 0.125f;
        m[qq] = -3.4e38f; den[qq] = 0.f; a0[qq] = 0.f; a1[qq] = 0.f;
    }

    const int kmax   = qbase + 63 + OFF + 1;
    const int nfull  = (qbase + OFF + 1) / 32;
    const int ntiles = (kmax + 31) / 32;

    for (int t = 0; t < ntiles; t++) {
        const int jt = t * 32;
        __syncthreads();
#pragma unroll
        for (int r = 0; r < 4; r++) {
            int rr = wid * 4 + r;
            int j = jt + rr;
            const float *kp, *vp;
            if (CROSS) {
                const float* base = (j < PFX) ? (kv0 + (size_t)j * 2048)
                                              : (kv1 + (size_t)(j - PFX) * 2048);
                kp = base + hbase; vp = base + INNER + hbase;
            } else {
                kp = kv0 + (size_t)j * 3072 + INNER + hbase;
                vp = kp + INNER;
            }
            if (lane < 16)
                *reinterpret_cast<float4*>(&Ks[rr][lane * 4]) =
                    *reinterpret_cast<const float4*>(kp + lane * 4);
            else
                *reinterpret_cast<float4*>(&Vs[rr][(lane - 16) * 4]) =
                    *reinterpret_cast<const float4*>(vp + (lane - 16) * 4);
        }
        __syncthreads();

        if (t < nfull) {
            for (int kk = 0; kk < 32; kk++) {
                float k0 = Ks[kk][lane], k1 = Ks[kk][lane + 32];
                float v0 = Vs[kk][lane], v1 = Vs[kk][lane + 32];
#pragma unroll
                for (int qq = 0; qq < 8; qq++) {
                    float pd = q0[qq] * k0 + q1[qq] * k1;
#pragma unroll
                    for (int o = 16; o; o >>= 1)
                        pd += __shfl_xor_sync(0xffffffffu, pd, o);
                    float mn = fmaxf(m[qq], pd);
                    float cc = __expf(m[qq] - mn);
                    float p = __expf(pd - mn);
                    den[qq] = den[qq] * cc + p;
                    a0[qq]  = a0[qq]  * cc + p * v0;
                    a1[qq]  = a1[qq]  * cc + p * v1;
                    m[qq] = mn;
                }
            }
        } else {
            for (int kk = 0; kk < 32; kk++) {
                int j = jt + kk;
                float k0 = Ks[kk][lane], k1 = Ks[kk][lane + 32];
                float v0 = Vs[kk][lane], v1 = Vs[kk][lane + 32];
#pragma unroll
                for (int qq = 0; qq < 8; qq++) {
                    if (j > ibase + qq + OFF) continue;
                    float pd = q0[qq] * k0 + q1[qq] * k1;
#pragma unroll
                    for (int o = 16; o; o >>= 1)
                        pd += __shfl_xor_sync(0xffffffffu, pd, o);
                    float mn = fmaxf(m[qq], pd);
                    float cc = __expf(m[qq] - mn);
                    float p = __expf(pd - mn);
                    den[qq] = den[qq] * cc + p;
                    a0[qq]  = a0[qq]  * cc + p * v0;
                    a1[qq]  = a1[qq]  * cc + p * v1;
                    m[qq] = mn;
                }
            }
        }
    }

#pragma unroll
    for (int qq = 0; qq < 8; qq++) {
        float r = 1.f / den[qq];
        out[(size_t)(ibase + qq) * INNER + hbase + lane]      = a0[qq] * r;
        out[(size_t)(ibase + qq) * INNER + hbase + lane + 32] = a1[qq] * r;
    }
}

// ---------------------------------------------------------------------------
// Host orchestration
// ---------------------------------------------------------------------------
static void run_sgemm(int epi, const float* A, const float* B, float* C,
                      const float* bias, const float* res, int M, int Nn, int K)
{
    dim3 grid(Nn / 128, M / 128);
    switch (epi) {
        case 0: sgemm_kernel<0><<<grid, 256>>>(A, B, C, bias, res, M, Nn, K); break;
        case 1: sgemm_kernel<1><<<grid, 256>>>(A, B, C, bias, res, M, Nn, K); break;
        case 2: sgemm_kernel<2><<<grid, 256>>>(A, B, C, bias, res, M, Nn, K); break;
        case 3: sgemm_kernel<3><<<grid, 256>>>(A, B, C, bias, res, M, Nn, K); break;
    }
}

extern "C" void kernel_launch(void* const* d_in, const int* in_sizes, int n_in,
                              void* d_out, int out_size)
{
    (void)in_sizes; (void)n_in; (void)out_size;

    const int*   x        = (const int*)  d_in[0];
    const float* tok_emb  = (const float*)d_in[1];
    const float* pos_emb  = (const float*)d_in[2];
    const float* ca_ln_g  = (const float*)d_in[3];
    const float* ca_ln_b  = (const float*)d_in[4];
    const float* ca_wq    = (const float*)d_in[5];
    const float* ca_wkv   = (const float*)d_in[6];
    const float* ca_wo    = (const float*)d_in[7];
    const float* ca_bo    = (const float*)d_in[8];
    const float* cf_ln_g  = (const float*)d_in[9];
    const float* cf_ln_b  = (const float*)d_in[10];
    const float* cf_w1    = (const float*)d_in[11];
    const float* cf_w2    = (const float*)d_in[12];
    const float* la_ln_g  = (const float*)d_in[13];
    const float* la_ln_b  = (const float*)d_in[14];
    const float* la_wqkv  = (const float*)d_in[15];
    const float* la_wo    = (const float*)d_in[16];
    const float* lf_ln_g  = (const float*)d_in[17];
    const float* lf_ln_b  = (const float*)d_in[18];
    const float* lf_w1    = (const float*)d_in[19];
    const float* lf_w2    = (const float*)d_in[20];
    const float* w_logits = (const float*)d_in[21];
    float* out = (float*)d_out;

    float *prefix, *h, *xn, *q, *kvin, *kvctx, *attn, *ff, *qkv;
    cudaGetSymbolAddress((void**)&prefix, g_prefix);
    cudaGetSymbolAddress((void**)&h,      g_h);
    cudaGetSymbolAddress((void**)&xn,     g_xn);
    cudaGetSymbolAddress((void**)&q,      g_q);
    cudaGetSymbolAddress((void**)&kvin,   g_kvin);
    cudaGetSymbolAddress((void**)&kvctx,  g_kvctx);
    cudaGetSymbolAddress((void**)&attn,   g_attn);
    cudaGetSymbolAddress((void**)&ff,     g_ff);
    cudaGetSymbolAddress((void**)&qkv,    g_qkv);

    // 1. Embedding
    embed_kernel<<<(NCTX * DMODEL) / 256, 256>>>(x, tok_emb, pos_emb);

    // 2. Cross-attention block
    ln_kernel<<<LAT, 256>>>(h, xn, ca_ln_g, ca_ln_b);
    run_sgemm(0, xn,     ca_wq,  q,     nullptr, nullptr, LAT, INNER,     DMODEL);
    run_sgemm(0, xn,     ca_wkv, kvin,  nullptr, nullptr, LAT, 2 * INNER, DMODEL);
    run_sgemm(0, prefix, ca_wkv, kvctx, nullptr, nullptr, PFX, 2 * INNER, DMODEL);
    {
        dim3 g(LAT / 64, NHEAD);
        attn_kernel<1><<<g, 256>>>(q, kvctx, kvin, attn);
    }
    run_sgemm(1, attn, ca_wo, h, ca_bo, h, LAT, DMODEL, INNER);

    // 3. Cross FFN
    ln_kernel<<<LAT, 256>>>(h, xn, cf_ln_g, cf_ln_b);
    run_sgemm(3, xn, cf_w1, ff, nullptr, nullptr, LAT, FFDIM, DMODEL);
    run_sgemm(2, ff, cf_w2, h, nullptr, h, LAT, DMODEL, FFDIM);

    // 4. Latent self-attention layers
    for (int l = 0; l < DEPTH; l++) {
        ln_kernel<<<LAT, 256>>>(h, xn, la_ln_g + (size_t)l * DMODEL, la_ln_b + (size_t)l * DMODEL);
        run_sgemm(0, xn, la_wqkv + (size_t)l * DMODEL * 3 * INNER, qkv,
                  nullptr, nullptr, LAT, 3 * INNER, DMODEL);
        {
            dim3 g(LAT / 64, NHEAD);
            attn_kernel<0><<<g, 256>>>(qkv, qkv, nullptr, attn);
        }
        run_sgemm(2, attn, la_wo + (size_t)l * INNER * DMODEL, h, nullptr, h, LAT, DMODEL, INNER);

        ln_kernel<<<LAT, 256>>>(h, xn, lf_ln_g + (size_t)l * DMODEL, lf_ln_b + (size_t)l * DMODEL);
        run_sgemm(3, xn, lf_w1 + (size_t)l * DMODEL * FFDIM, ff, nullptr, nullptr, LAT, FFDIM, DMODEL);
        run_sgemm(2, ff, lf_w2 + (size_t)l * FFDIM * DMODEL, h, nullptr, h, LAT, DMODEL, FFDIM);
    }

    // 5. Logits
    run_sgemm(0, h, w_logits, out, nullptr, nullptr, LAT, VOCAB, DMODEL);
}

// round 6
// speedup vs baseline: 2.6667x; 1.7307x over previous
#include <cuda_runtime.h>
#include <cuda_bf16.h>
#include <math.h>
#include <stdint.h>

// Problem constants
#define NCTX   4096
#define DMODEL 1024
#define NHEAD  16
#define DHEAD  64
#define DEPTH  4
#define PFX    3072
#define LAT    1024          // NCTX - PFX
#define FFDIM  4096
#define VOCAB  32000
#define INNER  1024          // NHEAD * DHEAD

// ---------------------------------------------------------------------------
// Scratch (static __device__ globals; no runtime allocation)
// ---------------------------------------------------------------------------
__device__ float g_prefix[PFX * DMODEL];
__device__ float g_h     [LAT * DMODEL];
__device__ float g_xn    [LAT * DMODEL];
__device__ float g_q     [LAT * INNER];
__device__ float g_kvin  [LAT * 2 * INNER];
__device__ float g_kvctx [PFX * 2 * INNER];
__device__ float g_attn  [LAT * INNER];
__device__ float g_ff    [LAT * FFDIM];
__device__ float g_qkv   [LAT * 3 * INNER];

// ---------------------------------------------------------------------------
// Embedding
// ---------------------------------------------------------------------------
__global__ void embed_kernel(const int* __restrict__ x,
                             const float* __restrict__ tok,
                             const float* __restrict__ pos)
{
    int idx = blockIdx.x * blockDim.x + threadIdx.x;
    int n = idx >> 10;
    int d = idx & 1023;
    float v = tok[(size_t)x[n] * DMODEL + d] + pos[idx];
    if (n < PFX) g_prefix[(size_t)n * DMODEL + d] = v;
    else         g_h[(size_t)(n - PFX) * DMODEL + d] = v;
}

// ---------------------------------------------------------------------------
// LayerNorm (D=1024), one block per row
// ---------------------------------------------------------------------------
__global__ __launch_bounds__(256) void ln_kernel(
    const float* __restrict__ in, float* __restrict__ out,
    const float* __restrict__ g, const float* __restrict__ b)
{
    int row = blockIdx.x;
    const float* p = in + (size_t)row * DMODEL;
    float vals[4];
    float s = 0.f, s2 = 0.f;
#pragma unroll
    for (int u = 0; u < 4; u++) {
        float v = p[threadIdx.x + u * 256];
        vals[u] = v; s += v; s2 += v * v;
    }
#pragma unroll
    for (int o = 16; o; o >>= 1) {
        s  += __shfl_xor_sync(0xffffffffu, s,  o);
        s2 += __shfl_xor_sync(0xffffffffu, s2, o);
    }
    __shared__ float sh[2][8];
    int wid = threadIdx.x >> 5, lane = threadIdx.x & 31;
    if (lane == 0) { sh[0][wid] = s; sh[1][wid] = s2; }
    __syncthreads();
    s = 0.f; s2 = 0.f;
#pragma unroll
    for (int w = 0; w < 8; w++) { s += sh[0][w]; s2 += sh[1][w]; }
    float mean = s * (1.f / DMODEL);
    float var  = s2 * (1.f / DMODEL) - mean * mean;
    float inv  = rsqrtf(var + 1e-5f);
#pragma unroll
    for (int u = 0; u < 4; u++) {
        int d = threadIdx.x + u * 256;
        out[(size_t)row * DMODEL + d] = (vals[u] - mean) * inv * g[d] + b[d];
    }
}

// ---------------------------------------------------------------------------
// TF32 tensor-core GEMM: C[M,N] = A[M,K] @ B[K,N]  (row-major)
// mma.sync.m16n8k8 tf32, fp32 accumulate.
// Block tile 128x128, BK=16, 512 threads = 16 warps (4 M x 4 N),
// warp tile 32x32 (2 m-frags x 4 n-frags). Double-buffered smem, pitch 132.
// Epilogues: 0 none | 1 +bias[col]+res | 2 +res | 3 exact GELU
// ---------------------------------------------------------------------------
#define BK 16
#define SPITCH 132

__device__ __forceinline__ uint32_t f2tf(float x) {
    uint32_t r;
    asm("cvt.rna.tf32.f32 %0, %1;" : "=r"(r) : "f"(x));
    return r;
}

__device__ __forceinline__ void mma_tf32(float* d, const uint32_t* a, const uint32_t* b) {
    asm volatile(
        "mma.sync.aligned.m16n8k8.row.col.f32.tf32.tf32.f32 "
        "{%0,%1,%2,%3}, {%4,%5,%6,%7}, {%8,%9}, {%0,%1,%2,%3};"
        : "+f"(d[0]), "+f"(d[1]), "+f"(d[2]), "+f"(d[3])
        : "r"(a[0]), "r"(a[1]), "r"(a[2]), "r"(a[3]), "r"(b[0]), "r"(b[1]));
}

template <int EPI>
__global__ __launch_bounds__(512) void sgemm_kernel(
    const float* __restrict__ A, const float* __restrict__ B,
    float* __restrict__ C, const float* __restrict__ bias,
    const float* __restrict__ res, int M, int Nn, int K)
{
    __shared__ uint32_t As[2][BK][SPITCH];
    __shared__ uint32_t Bs[2][BK][SPITCH];

    const int tid  = threadIdx.x;
    const int lane = tid & 31, wid = tid >> 5;       // 16 warps
    const int g = lane >> 2, c = lane & 3;
    const int wm = (wid & 3) * 32;                   // warp M offset
    const int wn = (wid >> 2) * 32;                  // warp N offset
    const int bx = blockIdx.x, by = blockIdx.y;

    // Global load mapping: 1 float4 of A + 1 float4 of B per thread per tile
    const int arow  = tid >> 2;          // 0..127
    const int acol  = (tid & 3) * 4;     // k offset 0,4,8,12
    const int bkrow = tid >> 5;          // 0..15
    const int bncol = (tid & 31) * 4;    // 0..124

    const float* Ap = A + (size_t)(by * 128 + arow) * K + acol;
    const float* Bp = B + (size_t)bkrow * Nn + bx * 128 + bncol;

    float acc[2][4][4];
#pragma unroll
    for (int mf = 0; mf < 2; mf++)
#pragma unroll
        for (int nf = 0; nf < 4; nf++)
#pragma unroll
            for (int i = 0; i < 4; i++) acc[mf][nf][i] = 0.f;

    const int nt = K / BK;

    float4 pa, pb;
    pa = *reinterpret_cast<const float4*>(Ap);
    pb = *reinterpret_cast<const float4*>(Bp);
    {
        As[0][acol + 0][arow] = f2tf(pa.x);
        As[0][acol + 1][arow] = f2tf(pa.y);
        As[0][acol + 2][arow] = f2tf(pa.z);
        As[0][acol + 3][arow] = f2tf(pa.w);
        Bs[0][bkrow][bncol + 0] = f2tf(pb.x);
        Bs[0][bkrow][bncol + 1] = f2tf(pb.y);
        Bs[0][bkrow][bncol + 2] = f2tf(pb.z);
        Bs[0][bkrow][bncol + 3] = f2tf(pb.w);
    }
    __syncthreads();

    for (int kt = 0; kt < nt; kt++) {
        const int cur = kt & 1;
        if (kt + 1 < nt) {
            pa = *reinterpret_cast<const float4*>(Ap + (size_t)(kt + 1) * BK);
            pb = *reinterpret_cast<const float4*>(Bp + (size_t)(kt + 1) * BK * Nn);
        }

#pragma unroll
        for (int ks = 0; ks < 2; ks++) {
            const int k0 = ks * 8;
            uint32_t af[2][4], bf[4][2];
#pragma unroll
            for (int mf = 0; mf < 2; mf++) {
                int mrow = wm + mf * 16 + g;
                af[mf][0] = As[cur][k0 + c][mrow];
                af[mf][1] = As[cur][k0 + c][mrow + 8];
                af[mf][2] = As[cur][k0 + c + 4][mrow];
                af[mf][3] = As[cur][k0 + c + 4][mrow + 8];
            }
#pragma unroll
            for (int nf = 0; nf < 4; nf++) {
                int ncol = wn + nf * 8 + g;
                bf[nf][0] = Bs[cur][k0 + c][ncol];
                bf[nf][1] = Bs[cur][k0 + c + 4][ncol];
            }
#pragma unroll
            for (int mf = 0; mf < 2; mf++)
#pragma unroll
                for (int nf = 0; nf < 4; nf++)
                    mma_tf32(acc[mf][nf], af[mf], bf[nf]);
        }

        if (kt + 1 < nt) {
            const int nxt = cur ^ 1;
            As[nxt][acol + 0][arow] = f2tf(pa.x);
            As[nxt][acol + 1][arow] = f2tf(pa.y);
            As[nxt][acol + 2][arow] = f2tf(pa.z);
            As[nxt][acol + 3][arow] = f2tf(pa.w);
            Bs[nxt][bkrow][bncol + 0] = f2tf(pb.x);
            Bs[nxt][bkrow][bncol + 1] = f2tf(pb.y);
            Bs[nxt][bkrow][bncol + 2] = f2tf(pb.z);
            Bs[nxt][bkrow][bncol + 3] = f2tf(pb.w);
            __syncthreads();
        }
    }

    // Epilogue: C fragment c0:(g,2c) c1:(g,2c+1) c2:(g+8,2c) c3:(g+8,2c+1)
#pragma unroll
    for (int mf = 0; mf < 2; mf++) {
#pragma unroll
        for (int nf = 0; nf < 4; nf++) {
            int row = by * 128 + wm + mf * 16 + g;
            int col = bx * 128 + wn + nf * 8 + 2 * c;
#pragma unroll
            for (int half = 0; half < 2; half++) {
                int r = row + half * 8;
                float v0 = acc[mf][nf][half * 2 + 0];
                float v1 = acc[mf][nf][half * 2 + 1];
                if (EPI == 1) {
                    v0 += bias[col]     + res[(size_t)r * Nn + col];
                    v1 += bias[col + 1] + res[(size_t)r * Nn + col + 1];
                }
                if (EPI == 2) {
                    v0 += res[(size_t)r * Nn + col];
                    v1 += res[(size_t)r * Nn + col + 1];
                }
                if (EPI == 3) {
                    v0 = 0.5f * v0 * (1.f + erff(v0 * 0.70710678f));
                    v1 = 0.5f * v1 * (1.f + erff(v1 * 0.70710678f));
                }
                float2 o = make_float2(v0, v1);
                *reinterpret_cast<float2*>(C + (size_t)r * Nn + col) = o;
            }
        }
    }
}

// ---------------------------------------------------------------------------
// Tiled attention, shuffle-light version.
// Block = (head, 64-query tile), 8 warps x 8 queries.
// Per 32-key tile:
//   Phase A (lane=key): s[q] = dot(Q[q], K[lane]) via KT[d][key] smem
//                       (transposed, pitch 33 -> conflict-free) + Q broadcast.
//   Phase B: per-q warp max (5 shfl), lane-parallel exp, per-lane partial den.
//   Phase C (lane=dim): acc[d] += p[key]*V[key][d], p via per-warp smem Ps.
// Causal mask folds in as s = -FLT_MAX -> p = 0.
// ---------------------------------------------------------------------------
template <int CROSS>
__global__ __launch_bounds__(256) void attn_kernel(
    const float* __restrict__ qsrc, const float* __restrict__ kv0,
    const float* __restrict__ kv1, float* __restrict__ out)
{
    const int OFF     = CROSS ? PFX : 0;
    const int QSTRIDE = CROSS ? INNER : 3 * INNER;

    const int hbase = blockIdx.y * DHEAD;
    const int qbase = blockIdx.x * 64;
    const int wid = threadIdx.x >> 5, lane = threadIdx.x & 31;
    const int ibase = qbase + wid * 8;

    __shared__ float Qs[64][64];    // queries (pre-scaled)
    __shared__ float KT[64][33];    // K transposed [d][key], pad 33
    __shared__ float Vs[32][64];    // V row-major [key][d]
    __shared__ float Ps[8][8][32];  // per-warp p staging [warp][q][key]

    // Load Q tile (scaled by 1/8): 4096 floats, 4 float4 per thread
    {
        int qr = threadIdx.x >> 2;
        int c0 = (threadIdx.x & 3) * 4;
        const float* qp = qsrc + (size_t)(qbase + qr) * QSTRIDE + hbase;
#pragma unroll
        for (int u = 0; u < 4; u++) {
            float4 v = *reinterpret_cast<const float4*>(qp + c0 + u * 16);
            Qs[qr][c0 + u * 16 + 0] = v.x * 0.125f;
            Qs[qr][c0 + u * 16 + 1] = v.y * 0.125f;
            Qs[qr][c0 + u * 16 + 2] = v.z * 0.125f;
            Qs[qr][c0 + u * 16 + 3] = v.w * 0.125f;
        }
    }

    float m[8], den[8], acc0[8], acc1[8], cs[8];
#pragma unroll
    for (int qq = 0; qq < 8; qq++) {
        m[qq] = -3.0e38f; den[qq] = 0.f; acc0[qq] = 0.f; acc1[qq] = 0.f;
    }

    const int kmax   = qbase + 63 + OFF + 1;   // exclusive key bound for block
    const int nfull  = (qbase + OFF + 1) / 32; // tiles valid for ALL queries
    const int ntiles = (kmax + 31) / 32;

    for (int t = 0; t < ntiles; t++) {
        const int jt = t * 32;
        __syncthreads();
        // Stage K (transposed) and V: thread -> key = tid>>3, d0 = (tid&7)*8
        {
            int key = threadIdx.x >> 3;
            int d0  = (threadIdx.x & 7) * 8;
            int j = jt + key;
            const float *kp, *vp;
            if (CROSS) {
                const float* base = (j < PFX) ? (kv0 + (size_t)j * 2048)
                                              : (kv1 + (size_t)(j - PFX) * 2048);
                kp = base + hbase; vp = base + INNER + hbase;
            } else {
                kp = kv0 + (size_t)j * 3072 + INNER + hbase;
                vp = kp + INNER;
            }
            float4 ka = *reinterpret_cast<const float4*>(kp + d0);
            float4 kb = *reinterpret_cast<const float4*>(kp + d0 + 4);
            KT[d0 + 0][key] = ka.x; KT[d0 + 1][key] = ka.y;
            KT[d0 + 2][key] = ka.z; KT[d0 + 3][key] = ka.w;
            KT[d0 + 4][key] = kb.x; KT[d0 + 5][key] = kb.y;
            KT[d0 + 6][key] = kb.z; KT[d0 + 7][key] = kb.w;
            *reinterpret_cast<float4*>(&Vs[key][d0])     =
                *reinterpret_cast<const float4*>(vp + d0);
            *reinterpret_cast<float4*>(&Vs[key][d0 + 4]) =
                *reinterpret_cast<const float4*>(vp + d0 + 4);
        }
        __syncthreads();

        // Phase A: scores, lane = key
        float s[8];
#pragma unroll
        for (int qq = 0; qq < 8; qq++) s[qq] = 0.f;
#pragma unroll
        for (int dv = 0; dv < 16; dv++) {
            const int d = dv * 4;
            float k0 = KT[d + 0][lane];
            float k1 = KT[d + 1][lane];
            float k2 = KT[d + 2][lane];
            float k3 = KT[d + 3][lane];
#pragma unroll
            for (int qq = 0; qq < 8; qq++) {
                float4 q4 = *reinterpret_cast<const float4*>(&Qs[wid * 8 + qq][d]);
                s[qq] += q4.x * k0 + q4.y * k1 + q4.z * k2 + q4.w * k3;
            }
        }

        // Phase B: online softmax bookkeeping
        const bool bound = (t >= nfull);
#pragma unroll
        for (int qq = 0; qq < 8; qq++) {
            float sv = s[qq];
            if (bound && (jt + lane > ibase + qq + OFF)) sv = -3.0e38f;
            float mx = sv;
#pragma unroll
            for (int o = 16; o; o >>= 1)
                mx = fmaxf(mx, __shfl_xor_sync(0xffffffffu, mx, o));
            float mn = fmaxf(m[qq], mx);
            float cc = __expf(m[qq] - mn);
            float p  = __expf(sv - mn);
            den[qq] = den[qq] * cc + p;   // per-lane partial
            cs[qq] = cc;
            m[qq] = mn;
            Ps[wid][qq][lane] = p;
        }
        __syncwarp();

        // Phase C: V accumulation, lane = dim
#pragma unroll
        for (int qq = 0; qq < 8; qq++) { acc0[qq] *= cs[qq]; acc1[qq] *= cs[qq]; }
#pragma unroll 4
        for (int k = 0; k < 32; k++) {
            float v0 = Vs[k][lane], v1 = Vs[k][lane + 32];
#pragma unroll
            for (int qq = 0; qq < 8; qq++) {
                float p = Ps[wid][qq][k];
                acc0[qq] += p * v0;
                acc1[qq] += p * v1;
            }
        }
    }

#pragma unroll
    for (int qq = 0; qq < 8; qq++) {
        float d = den[qq];
#pragma unroll
        for (int o = 16; o; o >>= 1)
            d += __shfl_xor_sync(0xffffffffu, d, o);
        float r = 1.f / d;
        out[(size_t)(ibase + qq) * INNER + hbase + lane]      = acc0[qq] * r;
        out[(size_t)(ibase + qq) * INNER + hbase + lane + 32] = acc1[qq] * r;
    }
}

// ---------------------------------------------------------------------------
// Host orchestration
// ---------------------------------------------------------------------------
static void run_sgemm(int epi, const float* A, const float* B, float* C,
                      const float* bias, const float* res, int M, int Nn, int K)
{
    dim3 grid(Nn / 128, M / 128);
    switch (epi) {
        case 0: sgemm_kernel<0><<<grid, 512>>>(A, B, C, bias, res, M, Nn, K); break;
        case 1: sgemm_kernel<1><<<grid, 512>>>(A, B, C, bias, res, M, Nn, K); break;
        case 2: sgemm_kernel<2><<<grid, 512>>>(A, B, C, bias, res, M, Nn, K); break;
        case 3: sgemm_kernel<3><<<grid, 512>>>(A, B, C, bias, res, M, Nn, K); break;
    }
}

extern "C" void kernel_launch(void* const* d_in, const int* in_sizes, int n_in,
                              void* d_out, int out_size)
{
    (void)in_sizes; (void)n_in; (void)out_size;

    const int*   x        = (const int*)  d_in[0];
    const float* tok_emb  = (const float*)d_in[1];
    const float* pos_emb  = (const float*)d_in[2];
    const float* ca_ln_g  = (const float*)d_in[3];
    const float* ca_ln_b  = (const float*)d_in[4];
    const float* ca_wq    = (const float*)d_in[5];
    const float* ca_wkv   = (const float*)d_in[6];
    const float* ca_wo    = (const float*)d_in[7];
    const float* ca_bo    = (const float*)d_in[8];
    const float* cf_ln_g  = (const float*)d_in[9];
    const float* cf_ln_b  = (const float*)d_in[10];
    const float* cf_w1    = (const float*)d_in[11];
    const float* cf_w2    = (const float*)d_in[12];
    const float* la_ln_g  = (const float*)d_in[13];
    const float* la_ln_b  = (const float*)d_in[14];
    const float* la_wqkv  = (const float*)d_in[15];
    const float* la_wo    = (const float*)d_in[16];
    const float* lf_ln_g  = (const float*)d_in[17];
    const float* lf_ln_b  = (const float*)d_in[18];
    const float* lf_w1    = (const float*)d_in[19];
    const float* lf_w2    = (const float*)d_in[20];
    const float* w_logits = (const float*)d_in[21];
    float* out = (float*)d_out;

    float *prefix, *h, *xn, *q, *kvin, *kvctx, *attn, *ff, *qkv;
    cudaGetSymbolAddress((void**)&prefix, g_prefix);
    cudaGetSymbolAddress((void**)&h,      g_h);
    cudaGetSymbolAddress((void**)&xn,     g_xn);
    cudaGetSymbolAddress((void**)&q,      g_q);
    cudaGetSymbolAddress((void**)&kvin,   g_kvin);
    cudaGetSymbolAddress((void**)&kvctx,  g_kvctx);
    cudaGetSymbolAddress((void**)&attn,   g_attn);
    cudaGetSymbolAddress((void**)&ff,     g_ff);
    cudaGetSymbolAddress((void**)&qkv,    g_qkv);

    // 1. Embedding
    embed_kernel<<<(NCTX * DMODEL) / 256, 256>>>(x, tok_emb, pos_emb);

    // 2. Cross-attention block
    ln_kernel<<<LAT, 256>>>(h, xn, ca_ln_g, ca_ln_b);
    run_sgemm(0, xn,     ca_wq,  q,     nullptr, nullptr, LAT, INNER,     DMODEL);
    run_sgemm(0, xn,     ca_wkv, kvin,  nullptr, nullptr, LAT, 2 * INNER, DMODEL);
    run_sgemm(0, prefix, ca_wkv, kvctx, nullptr, nullptr, PFX, 2 * INNER, DMODEL);
    {
        dim3 g(LAT / 64, NHEAD);
        attn_kernel<1><<<g, 256>>>(q, kvctx, kvin, attn);
    }
    run_sgemm(1, attn, ca_wo, h, ca_bo, h, LAT, DMODEL, INNER);

    // 3. Cross FFN
    ln_kernel<<<LAT, 256>>>(h, xn, cf_ln_g, cf_ln_b);
    run_sgemm(3, xn, cf_w1, ff, nullptr, nullptr, LAT, FFDIM, DMODEL);
    run_sgemm(2, ff, cf_w2, h, nullptr, h, LAT, DMODEL, FFDIM);

    // 4. Latent self-attention layers
    for (int l = 0; l < DEPTH; l++) {
        ln_kernel<<<LAT, 256>>>(h, xn, la_ln_g + (size_t)l * DMODEL, la_ln_b + (size_t)l * DMODEL);
        run_sgemm(0, xn, la_wqkv + (size_t)l * DMODEL * 3 * INNER, qkv,
                  nullptr, nullptr, LAT, 3 * INNER, DMODEL);
        {
            dim3 g(LAT / 64, NHEAD);
            attn_kernel<0><<<g, 256>>>(qkv, qkv, nullptr, attn);
        }
        run_sgemm(2, attn, la_wo + (size_t)l * INNER * DMODEL, h, nullptr, h, LAT, DMODEL, INNER);

        ln_kernel<<<LAT, 256>>>(h, xn, lf_ln_g + (size_t)l * DMODEL, lf_ln_b + (size_t)l * DMODEL);
        run_sgemm(3, xn, lf_w1 + (size_t)l * DMODEL * FFDIM, ff, nullptr, nullptr, LAT, FFDIM, DMODEL);
        run_sgemm(2, ff, lf_w2 + (size_t)l * FFDIM * DMODEL, h, nullptr, h, LAT, DMODEL, FFDIM);
    }

    // 5. Logits
    run_sgemm(0, h, w_logits, out, nullptr, nullptr, LAT, VOCAB, DMODEL);
}

// round 7
// speedup vs baseline: 3.4621x; 1.2983x over previous
#include <cuda_runtime.h>
#include <cuda_bf16.h>
#include <math.h>
#include <stdint.h>

// Problem constants
#define NCTX   4096
#define DMODEL 1024
#define NHEAD  16
#define DHEAD  64
#define DEPTH  4
#define PFX    3072
#define LAT    1024          // NCTX - PFX
#define FFDIM  4096
#define VOCAB  32000
#define INNER  1024          // NHEAD * DHEAD

// ---------------------------------------------------------------------------
// Scratch (static __device__ globals; no runtime allocation)
// ---------------------------------------------------------------------------
__device__ float g_prefix[PFX * DMODEL];
__device__ float g_h     [LAT * DMODEL];
__device__ float g_xn    [LAT * DMODEL];
__device__ float g_q     [LAT * INNER];
__device__ float g_kvin  [LAT * 2 * INNER];
__device__ float g_kvctx [PFX * 2 * INNER];
__device__ float g_attn  [LAT * INNER];
__device__ float g_ff    [LAT * FFDIM];
__device__ float g_qkv   [LAT * 3 * INNER];

// ---------------------------------------------------------------------------
// Embedding
// ---------------------------------------------------------------------------
__global__ void embed_kernel(const int* __restrict__ x,
                             const float* __restrict__ tok,
                             const float* __restrict__ pos)
{
    int idx = blockIdx.x * blockDim.x + threadIdx.x;
    int n = idx >> 10;
    int d = idx & 1023;
    float v = tok[(size_t)x[n] * DMODEL + d] + pos[idx];
    if (n < PFX) g_prefix[(size_t)n * DMODEL + d] = v;
    else         g_h[(size_t)(n - PFX) * DMODEL + d] = v;
}

// ---------------------------------------------------------------------------
// LayerNorm (D=1024), one block per row
// ---------------------------------------------------------------------------
__global__ __launch_bounds__(256) void ln_kernel(
    const float* __restrict__ in, float* __restrict__ out,
    const float* __restrict__ g, const float* __restrict__ b)
{
    int row = blockIdx.x;
    const float* p = in + (size_t)row * DMODEL;
    float vals[4];
    float s = 0.f, s2 = 0.f;
#pragma unroll
    for (int u = 0; u < 4; u++) {
        float v = p[threadIdx.x + u * 256];
        vals[u] = v; s += v; s2 += v * v;
    }
#pragma unroll
    for (int o = 16; o; o >>= 1) {
        s  += __shfl_xor_sync(0xffffffffu, s,  o);
        s2 += __shfl_xor_sync(0xffffffffu, s2, o);
    }
    __shared__ float sh[2][8];
    int wid = threadIdx.x >> 5, lane = threadIdx.x & 31;
    if (lane == 0) { sh[0][wid] = s; sh[1][wid] = s2; }
    __syncthreads();
    s = 0.f; s2 = 0.f;
#pragma unroll
    for (int w = 0; w < 8; w++) { s += sh[0][w]; s2 += sh[1][w]; }
    float mean = s * (1.f / DMODEL);
    float var  = s2 * (1.f / DMODEL) - mean * mean;
    float inv  = rsqrtf(var + 1e-5f);
#pragma unroll
    for (int u = 0; u < 4; u++) {
        int d = threadIdx.x + u * 256;
        out[(size_t)row * DMODEL + d] = (vals[u] - mean) * inv * g[d] + b[d];
    }
}

// ---------------------------------------------------------------------------
// TF32 tensor-core GEMM: C[M,N] = A[M,K] @ B[K,N]  (row-major)
// mma.sync.m16n8k8 tf32, fp32 accumulate.
// Block tile BMx128 (BM = 128 or 64), BK=16, 256 threads = 8 warps (2M x 4N),
// warp tile (BM/2)x32 -> MF x 4 fragments. Double-buffered smem.
// Pitch = BM+8 / 136 (== 8 mod 32) -> conflict-free fragment LDS for A and B.
// Epilogues: 0 none | 1 +bias[col]+res | 2 +res | 3 exact GELU
// ---------------------------------------------------------------------------
#define BK 16

__device__ __forceinline__ uint32_t f2tf(float x) {
    uint32_t r;
    asm("cvt.rna.tf32.f32 %0, %1;" : "=r"(r) : "f"(x));
    return r;
}

__device__ __forceinline__ void mma_tf32(float* d, const uint32_t* a, const uint32_t* b) {
    asm volatile(
        "mma.sync.aligned.m16n8k8.row.col.f32.tf32.tf32.f32 "
        "{%0,%1,%2,%3}, {%4,%5,%6,%7}, {%8,%9}, {%0,%1,%2,%3};"
        : "+f"(d[0]), "+f"(d[1]), "+f"(d[2]), "+f"(d[3])
        : "r"(a[0]), "r"(a[1]), "r"(a[2]), "r"(a[3]), "r"(b[0]), "r"(b[1]));
}

template <int BM, int EPI>
__global__ __launch_bounds__(256, 2) void sgemm_kernel(
    const float* __restrict__ A, const float* __restrict__ B,
    float* __restrict__ C, const float* __restrict__ bias,
    const float* __restrict__ res, int M, int Nn, int K)
{
    constexpr int MF = BM / 32;       // m-fragments per warp
    constexpr int AP = BM + 8;        // A smem pitch (== 8 mod 32)
    constexpr int BP = 136;           // B smem pitch (== 8 mod 32)
    __shared__ uint32_t As[2][BK][AP];
    __shared__ uint32_t Bs[2][BK][BP];

    const int tid  = threadIdx.x;
    const int lane = tid & 31, wid = tid >> 5;       // 8 warps
    const int g = lane >> 2, c = lane & 3;
    const int wm = (wid & 1) * (BM / 2);             // warp M offset
    const int wn = (wid >> 1) * 32;                  // warp N offset
    const int bx = blockIdx.x, by = blockIdx.y;

    // Global load mapping
    const int arow  = (BM == 128) ? (tid >> 1) : (tid >> 2);
    const int acol  = (BM == 128) ? ((tid & 1) * 8) : ((tid & 3) * 4);
    const int bkrow = tid >> 5;          // 0..7 (and +8)
    const int bncol = (tid & 31) * 4;    // 0..124

    const float* Ap = A + (size_t)(by * BM + arow) * K + acol;
    const float* Bp = B + (size_t)bkrow * Nn + bx * 128 + bncol;

    float acc[MF][4][4];
#pragma unroll
    for (int mf = 0; mf < MF; mf++)
#pragma unroll
        for (int nf = 0; nf < 4; nf++)
#pragma unroll
            for (int i = 0; i < 4; i++) acc[mf][nf][i] = 0.f;

    const int nt = K / BK;

    float4 pa0, pa1, pb0, pb1;
    pa0 = *reinterpret_cast<const float4*>(Ap);
    if (BM == 128) pa1 = *reinterpret_cast<const float4*>(Ap + 4);
    pb0 = *reinterpret_cast<const float4*>(Bp);
    pb1 = *reinterpret_cast<const float4*>(Bp + (size_t)8 * Nn);
    {
        As[0][acol + 0][arow] = f2tf(pa0.x);
        As[0][acol + 1][arow] = f2tf(pa0.y);
        As[0][acol + 2][arow] = f2tf(pa0.z);
        As[0][acol + 3][arow] = f2tf(pa0.w);
        if (BM == 128) {
            As[0][acol + 4][arow] = f2tf(pa1.x);
            As[0][acol + 5][arow] = f2tf(pa1.y);
            As[0][acol + 6][arow] = f2tf(pa1.z);
            As[0][acol + 7][arow] = f2tf(pa1.w);
        }
        Bs[0][bkrow][bncol + 0] = f2tf(pb0.x);
        Bs[0][bkrow][bncol + 1] = f2tf(pb0.y);
        Bs[0][bkrow][bncol + 2] = f2tf(pb0.z);
        Bs[0][bkrow][bncol + 3] = f2tf(pb0.w);
        Bs[0][bkrow + 8][bncol + 0] = f2tf(pb1.x);
        Bs[0][bkrow + 8][bncol + 1] = f2tf(pb1.y);
        Bs[0][bkrow + 8][bncol + 2] = f2tf(pb1.z);
        Bs[0][bkrow + 8][bncol + 3] = f2tf(pb1.w);
    }
    __syncthreads();

    for (int kt = 0; kt < nt; kt++) {
        const int cur = kt & 1;
        if (kt + 1 < nt) {
            const float* ap = Ap + (size_t)(kt + 1) * BK;
            const float* bp = Bp + (size_t)(kt + 1) * BK * Nn;
            pa0 = *reinterpret_cast<const float4*>(ap);
            if (BM == 128) pa1 = *reinterpret_cast<const float4*>(ap + 4);
            pb0 = *reinterpret_cast<const float4*>(bp);
            pb1 = *reinterpret_cast<const float4*>(bp + (size_t)8 * Nn);
        }

#pragma unroll
        for (int ks = 0; ks < 2; ks++) {
            const int k0 = ks * 8;
            uint32_t af[MF][4], bf[4][2];
#pragma unroll
            for (int mf = 0; mf < MF; mf++) {
                int mrow = wm + mf * 16 + g;
                af[mf][0] = As[cur][k0 + c][mrow];
                af[mf][1] = As[cur][k0 + c][mrow + 8];
                af[mf][2] = As[cur][k0 + c + 4][mrow];
                af[mf][3] = As[cur][k0 + c + 4][mrow + 8];
            }
#pragma unroll
            for (int nf = 0; nf < 4; nf++) {
                int ncol = wn + nf * 8 + g;
                bf[nf][0] = Bs[cur][k0 + c][ncol];
                bf[nf][1] = Bs[cur][k0 + c + 4][ncol];
            }
#pragma unroll
            for (int mf = 0; mf < MF; mf++)
#pragma unroll
                for (int nf = 0; nf < 4; nf++)
                    mma_tf32(acc[mf][nf], af[mf], bf[nf]);
        }

        if (kt + 1 < nt) {
            const int nxt = cur ^ 1;
            As[nxt][acol + 0][arow] = f2tf(pa0.x);
            As[nxt][acol + 1][arow] = f2tf(pa0.y);
            As[nxt][acol + 2][arow] = f2tf(pa0.z);
            As[nxt][acol + 3][arow] = f2tf(pa0.w);
            if (BM == 128) {
                As[nxt][acol + 4][arow] = f2tf(pa1.x);
                As[nxt][acol + 5][arow] = f2tf(pa1.y);
                As[nxt][acol + 6][arow] = f2tf(pa1.z);
                As[nxt][acol + 7][arow] = f2tf(pa1.w);
            }
            Bs[nxt][bkrow][bncol + 0] = f2tf(pb0.x);
            Bs[nxt][bkrow][bncol + 1] = f2tf(pb0.y);
            Bs[nxt][bkrow][bncol + 2] = f2tf(pb0.z);
            Bs[nxt][bkrow][bncol + 3] = f2tf(pb0.w);
            Bs[nxt][bkrow + 8][bncol + 0] = f2tf(pb1.x);
            Bs[nxt][bkrow + 8][bncol + 1] = f2tf(pb1.y);
            Bs[nxt][bkrow + 8][bncol + 2] = f2tf(pb1.z);
            Bs[nxt][bkrow + 8][bncol + 3] = f2tf(pb1.w);
            __syncthreads();
        }
    }

    // Epilogue: C fragment c0:(g,2c) c1:(g,2c+1) c2:(g+8,2c) c3:(g+8,2c+1)
#pragma unroll
    for (int mf = 0; mf < MF; mf++) {
#pragma unroll
        for (int nf = 0; nf < 4; nf++) {
            int row = by * BM + wm + mf * 16 + g;
            int col = bx * 128 + wn + nf * 8 + 2 * c;
#pragma unroll
            for (int half = 0; half < 2; half++) {
                int r = row + half * 8;
                float v0 = acc[mf][nf][half * 2 + 0];
                float v1 = acc[mf][nf][half * 2 + 1];
                if (EPI == 1) {
                    v0 += bias[col]     + res[(size_t)r * Nn + col];
                    v1 += bias[col + 1] + res[(size_t)r * Nn + col + 1];
                }
                if (EPI == 2) {
                    v0 += res[(size_t)r * Nn + col];
                    v1 += res[(size_t)r * Nn + col + 1];
                }
                if (EPI == 3) {
                    v0 = 0.5f * v0 * (1.f + erff(v0 * 0.70710678f));
                    v1 = 0.5f * v1 * (1.f + erff(v1 * 0.70710678f));
                }
                float2 o = make_float2(v0, v1);
                *reinterpret_cast<float2*>(C + (size_t)r * Nn + col) = o;
            }
        }
    }
}

// ---------------------------------------------------------------------------
// Tiled attention, shuffle-light version (unchanged from passing round 6).
// ---------------------------------------------------------------------------
template <int CROSS>
__global__ __launch_bounds__(256) void attn_kernel(
    const float* __restrict__ qsrc, const float* __restrict__ kv0,
    const float* __restrict__ kv1, float* __restrict__ out)
{
    const int OFF     = CROSS ? PFX : 0;
    const int QSTRIDE = CROSS ? INNER : 3 * INNER;

    const int hbase = blockIdx.y * DHEAD;
    const int qbase = blockIdx.x * 64;
    const int wid = threadIdx.x >> 5, lane = threadIdx.x & 31;
    const int ibase = qbase + wid * 8;

    __shared__ float Qs[64][64];    // queries (pre-scaled)
    __shared__ float KT[64][33];    // K transposed [d][key], pad 33
    __shared__ float Vs[32][64];    // V row-major [key][d]
    __shared__ float Ps[8][8][32];  // per-warp p staging [warp][q][key]

    {
        int qr = threadIdx.x >> 2;
        int c0 = (threadIdx.x & 3) * 4;
        const float* qp = qsrc + (size_t)(qbase + qr) * QSTRIDE + hbase;
#pragma unroll
        for (int u = 0; u < 4; u++) {
            float4 v = *reinterpret_cast<const float4*>(qp + c0 + u * 16);
            Qs[qr][c0 + u * 16 + 0] = v.x * 0.125f;
            Qs[qr][c0 + u * 16 + 1] = v.y * 0.125f;
            Qs[qr][c0 + u * 16 + 2] = v.z * 0.125f;
            Qs[qr][c0 + u * 16 + 3] = v.w * 0.125f;
        }
    }

    float m[8], den[8], acc0[8], acc1[8], cs[8];
#pragma unroll
    for (int qq = 0; qq < 8; qq++) {
        m[qq] = -3.0e38f; den[qq] = 0.f; acc0[qq] = 0.f; acc1[qq] = 0.f;
    }

    const int kmax   = qbase + 63 + OFF + 1;
    const int nfull  = (qbase + OFF + 1) / 32;
    const int ntiles = (kmax + 31) / 32;

    for (int t = 0; t < ntiles; t++) {
        const int jt = t * 32;
        __syncthreads();
        {
            int key = threadIdx.x >> 3;
            int d0  = (threadIdx.x & 7) * 8;
            int j = jt + key;
            const float *kp, *vp;
            if (CROSS) {
                const float* base = (j < PFX) ? (kv0 + (size_t)j * 2048)
                                              : (kv1 + (size_t)(j - PFX) * 2048);
                kp = base + hbase; vp = base + INNER + hbase;
            } else {
                kp = kv0 + (size_t)j * 3072 + INNER + hbase;
                vp = kp + INNER;
            }
            float4 ka = *reinterpret_cast<const float4*>(kp + d0);
            float4 kb = *reinterpret_cast<const float4*>(kp + d0 + 4);
            KT[d0 + 0][key] = ka.x; KT[d0 + 1][key] = ka.y;
            KT[d0 + 2][key] = ka.z; KT[d0 + 3][key] = ka.w;
            KT[d0 + 4][key] = kb.x; KT[d0 + 5][key] = kb.y;
            KT[d0 + 6][key] = kb.z; KT[d0 + 7][key] = kb.w;
            *reinterpret_cast<float4*>(&Vs[key][d0])     =
                *reinterpret_cast<const float4*>(vp + d0);
            *reinterpret_cast<float4*>(&Vs[key][d0 + 4]) =
                *reinterpret_cast<const float4*>(vp + d0 + 4);
        }
        __syncthreads();

        float s[8];
#pragma unroll
        for (int qq = 0; qq < 8; qq++) s[qq] = 0.f;
#pragma unroll
        for (int dv = 0; dv < 16; dv++) {
            const int d = dv * 4;
            float k0 = KT[d + 0][lane];
            float k1 = KT[d + 1][lane];
            float k2 = KT[d + 2][lane];
            float k3 = KT[d + 3][lane];
#pragma unroll
            for (int qq = 0; qq < 8; qq++) {
                float4 q4 = *reinterpret_cast<const float4*>(&Qs[wid * 8 + qq][d]);
                s[qq] += q4.x * k0 + q4.y * k1 + q4.z * k2 + q4.w * k3;
            }
        }

        const bool bound = (t >= nfull);
#pragma unroll
        for (int qq = 0; qq < 8; qq++) {
            float sv = s[qq];
            if (bound && (jt + lane > ibase + qq + OFF)) sv = -3.0e38f;
            float mx = sv;
#pragma unroll
            for (int o = 16; o; o >>= 1)
                mx = fmaxf(mx, __shfl_xor_sync(0xffffffffu, mx, o));
            float mn = fmaxf(m[qq], mx);
            float cc = __expf(m[qq] - mn);
            float p  = __expf(sv - mn);
            den[qq] = den[qq] * cc + p;
            cs[qq] = cc;
            m[qq] = mn;
            Ps[wid][qq][lane] = p;
        }
        __syncwarp();

#pragma unroll
        for (int qq = 0; qq < 8; qq++) { acc0[qq] *= cs[qq]; acc1[qq] *= cs[qq]; }
#pragma unroll 4
        for (int k = 0; k < 32; k++) {
            float v0 = Vs[k][lane], v1 = Vs[k][lane + 32];
#pragma unroll
            for (int qq = 0; qq < 8; qq++) {
                float p = Ps[wid][qq][k];
                acc0[qq] += p * v0;
                acc1[qq] += p * v1;
            }
        }
    }

#pragma unroll
    for (int qq = 0; qq < 8; qq++) {
        float d = den[qq];
#pragma unroll
        for (int o = 16; o; o >>= 1)
            d += __shfl_xor_sync(0xffffffffu, d, o);
        float r = 1.f / d;
        out[(size_t)(ibase + qq) * INNER + hbase + lane]      = acc0[qq] * r;
        out[(size_t)(ibase + qq) * INNER + hbase + lane + 32] = acc1[qq] * r;
    }
}

// ---------------------------------------------------------------------------
// Host orchestration
// ---------------------------------------------------------------------------
static void run_sgemm(int epi, const float* A, const float* B, float* C,
                      const float* bias, const float* res, int M, int Nn, int K)
{
    int g128 = (Nn / 128) * (M / 128);
    if (g128 <= 64) {
        // small grid: BM=64 doubles block count to fill the chip
        dim3 grid(Nn / 128, M / 64);
        switch (epi) {
            case 0: sgemm_kernel<64,0><<<grid, 256>>>(A, B, C, bias, res, M, Nn, K); break;
            case 1: sgemm_kernel<64,1><<<grid, 256>>>(A, B, C, bias, res, M, Nn, K); break;
            case 2: sgemm_kernel<64,2><<<grid, 256>>>(A, B, C, bias, res, M, Nn, K); break;
            case 3: sgemm_kernel<64,3><<<grid, 256>>>(A, B, C, bias, res, M, Nn, K); break;
        }
    } else {
        dim3 grid(Nn / 128, M / 128);
        switch (epi) {
            case 0: sgemm_kernel<128,0><<<grid, 256>>>(A, B, C, bias, res, M, Nn, K); break;
            case 1: sgemm_kernel<128,1><<<grid, 256>>>(A, B, C, bias, res, M, Nn, K); break;
            case 2: sgemm_kernel<128,2><<<grid, 256>>>(A, B, C, bias, res, M, Nn, K); break;
            case 3: sgemm_kernel<128,3><<<grid, 256>>>(A, B, C, bias, res, M, Nn, K); break;
        }
    }
}

extern "C" void kernel_launch(void* const* d_in, const int* in_sizes, int n_in,
                              void* d_out, int out_size)
{
    (void)in_sizes; (void)n_in; (void)out_size;

    const int*   x        = (const int*)  d_in[0];
    const float* tok_emb  = (const float*)d_in[1];
    const float* pos_emb  = (const float*)d_in[2];
    const float* ca_ln_g  = (const float*)d_in[3];
    const float* ca_ln_b  = (const float*)d_in[4];
    const float* ca_wq    = (const float*)d_in[5];
    const float* ca_wkv   = (const float*)d_in[6];
    const float* ca_wo    = (const float*)d_in[7];
    const float* ca_bo    = (const float*)d_in[8];
    const float* cf_ln_g  = (const float*)d_in[9];
    const float* cf_ln_b  = (const float*)d_in[10];
    const float* cf_w1    = (const float*)d_in[11];
    const float* cf_w2    = (const float*)d_in[12];
    const float* la_ln_g  = (const float*)d_in[13];
    const float* la_ln_b  = (const float*)d_in[14];
    const float* la_wqkv  = (const float*)d_in[15];
    const float* la_wo    = (const float*)d_in[16];
    const float* lf_ln_g  = (const float*)d_in[17];
    const float* lf_ln_b  = (const float*)d_in[18];
    const float* lf_w1    = (const float*)d_in[19];
    const float* lf_w2    = (const float*)d_in[20];
    const float* w_logits = (const float*)d_in[21];
    float* out = (float*)d_out;

    float *prefix, *h, *xn, *q, *kvin, *kvctx, *attn, *ff, *qkv;
    cudaGetSymbolAddress((void**)&prefix, g_prefix);
    cudaGetSymbolAddress((void**)&h,      g_h);
    cudaGetSymbolAddress((void**)&xn,     g_xn);
    cudaGetSymbolAddress((void**)&q,      g_q);
    cudaGetSymbolAddress((void**)&kvin,   g_kvin);
    cudaGetSymbolAddress((void**)&kvctx,  g_kvctx);
    cudaGetSymbolAddress((void**)&attn,   g_attn);
    cudaGetSymbolAddress((void**)&ff,     g_ff);
    cudaGetSymbolAddress((void**)&qkv,    g_qkv);

    // 1. Embedding
    embed_kernel<<<(NCTX * DMODEL) / 256, 256>>>(x, tok_emb, pos_emb);

    // 2. Cross-attention block
    ln_kernel<<<LAT, 256>>>(h, xn, ca_ln_g, ca_ln_b);
    run_sgemm(0, xn,     ca_wq,  q,     nullptr, nullptr, LAT, INNER,     DMODEL);
    run_sgemm(0, xn,     ca_wkv, kvin,  nullptr, nullptr, LAT, 2 * INNER, DMODEL);
    run_sgemm(0, prefix, ca_wkv, kvctx, nullptr, nullptr, PFX, 2 * INNER, DMODEL);
    {
        dim3 g(LAT / 64, NHEAD);
        attn_kernel<1><<<g, 256>>>(q, kvctx, kvin, attn);
    }
    run_sgemm(1, attn, ca_wo, h, ca_bo, h, LAT, DMODEL, INNER);

    // 3. Cross FFN
    ln_kernel<<<LAT, 256>>>(h, xn, cf_ln_g, cf_ln_b);
    run_sgemm(3, xn, cf_w1, ff, nullptr, nullptr, LAT, FFDIM, DMODEL);
    run_sgemm(2, ff, cf_w2, h, nullptr, h, LAT, DMODEL, FFDIM);

    // 4. Latent self-attention layers
    for (int l = 0; l < DEPTH; l++) {
        ln_kernel<<<LAT, 256>>>(h, xn, la_ln_g + (size_t)l * DMODEL, la_ln_b + (size_t)l * DMODEL);
        run_sgemm(0, xn, la_wqkv + (size_t)l * DMODEL * 3 * INNER, qkv,
                  nullptr, nullptr, LAT, 3 * INNER, DMODEL);
        {
            dim3 g(LAT / 64, NHEAD);
            attn_kernel<0><<<g, 256>>>(qkv, qkv, nullptr, attn);
        }
        run_sgemm(2, attn, la_wo + (size_t)l * INNER * DMODEL, h, nullptr, h, LAT, DMODEL, INNER);

        ln_kernel<<<LAT, 256>>>(h, xn, lf_ln_g + (size_t)l * DMODEL, lf_ln_b + (size_t)l * DMODEL);
        run_sgemm(3, xn, lf_w1 + (size_t)l * DMODEL * FFDIM, ff, nullptr, nullptr, LAT, FFDIM, DMODEL);
        run_sgemm(2, ff, lf_w2 + (size_t)l * FFDIM * DMODEL, h, nullptr, h, LAT, DMODEL, FFDIM);
    }

    // 5. Logits
    run_sgemm(0, h, w_logits, out, nullptr, nullptr, LAT, VOCAB, DMODEL);
}